// round 11
// baseline (speedup 1.0000x reference)
#include <cuda_runtime.h>
#include <cuda_fp16.h>
#include <cstdint>

// SO3Linear via mma.sync fp16 (HMMA), single-MMA scheme (calibrated rel_err ~3e-4).
// R9: 128-thread CTAs, 4 warps x (32 rows x 64 cols) fragment-reuse tiling:
// LDSM per k-step/CTA drops 32 -> 24 x4 (wf/MMA 2 -> 1.5). Same 48KB smem ->
// still 4 CTAs/SM. Barriers now 128-thread scope. Streaming hints (__ldcs A,
// __stcs out) protect L2 residency of the W images.

#define BATCH    16384
#define NUM_M    25
#define IN_F     128
#define OUT_F    128
#define TILE_B   64
#define NTILE    4
#define NTHREADS 128

// W image per l: 32KB = 2 k-chunks (k 0..63 | 64..127) of 128 rows x 128B.
#define W_L_BYTES   32768
#define W_CH_STRIDE 16384
// smem: W at 0 (32KB), A at 32KB (2 chunks x 8KB).
#define A_OFF       32768
#define A_CH_STRIDE 8192
#define SMEM_BYTES  49152

#define SWZ(b) ((b) ^ (((b) >> 3) & 0x70))

__device__ __align__(128) uint8_t g_wprep[5 * W_L_BYTES];

__device__ __forceinline__ uint32_t smem_u32(const void* p) {
    uint32_t a;
    asm("{ .reg .u64 t; cvta.to.shared.u64 t, %1; cvt.u32.u64 %0, t; }" : "=r"(a) : "l"(p));
    return a;
}

#define LDSM4(r, addr) \
    asm volatile("ldmatrix.sync.aligned.m8n8.x4.shared.b16 {%0,%1,%2,%3}, [%4];" \
        : "=r"((r)[0]), "=r"((r)[1]), "=r"((r)[2]), "=r"((r)[3]) : "r"(addr))

#define MMA_F16(c, a, b0_, b1_) \
    asm volatile("mma.sync.aligned.m16n8k16.row.col.f32.f16.f16.f32 " \
        "{%0,%1,%2,%3},{%4,%5,%6,%7},{%8,%9},{%0,%1,%2,%3};" \
        : "+f"((c)[0]), "+f"((c)[1]), "+f"((c)[2]), "+f"((c)[3]) \
        : "r"((a)[0]), "r"((a)[1]), "r"((a)[2]), "r"((a)[3]), "r"(b0_), "r"(b1_))

__device__ __forceinline__ uint32_t pack_h2(float x, float y) {
    __half2 p = __floats2half2_rn(x, y);
    return *reinterpret_cast<uint32_t*>(&p);
}

// ---- Prep: W[l] -> centered fp16, SW128 smem-image layout in global ----
__global__ void so3_prep_w(const float* __restrict__ w) {
    const int l   = blockIdx.x;
    const int tid = threadIdx.x;
    const float bound = 0.088388347648318447f;  // 1/sqrt(128)
    uint8_t* dst = g_wprep + (size_t)l * W_L_BYTES;
    const float* src = w + (size_t)l * OUT_F * IN_F;
#pragma unroll
    for (int it = 0; it < 16; ++it) {
        int li = it * 256 + tid;
        int r  = li >> 5;
        int q  = li & 31;
        uint32_t soff = (uint32_t)(q >> 4) * W_CH_STRIDE +
                        SWZ((uint32_t)(r * 128 + (q & 15) * 8));
        float4 v = *reinterpret_cast<const float4*>(src + (size_t)r * IN_F + q * 4);
        v.x -= bound; v.y -= bound; v.z -= bound; v.w -= bound;
        *reinterpret_cast<uint2*>(dst + soff) =
            make_uint2(pack_h2(v.x, v.y), pack_h2(v.z, v.w));
    }
}

// ---- Main kernel ----
__global__ __launch_bounds__(NTHREADS, 4)
void so3linear_hmma_kernel(const float* __restrict__ in,
                           const float* __restrict__ bias,
                           float* __restrict__ out) {
    extern __shared__ char smem[];
    const uint32_t sb = smem_u32(smem);

    const int tid  = threadIdx.x;
    const int wid  = tid >> 5;            // 0..3
    const int lane = tid & 31;
    const int m    = blockIdx.y;
    const int l    = (m >= 16) ? 4 : (m >= 9) ? 3 : (m >= 4) ? 2 : (m >= 1) ? 1 : 0;

    // ---- W: flat 32KB cp.async from prepped image ----
    {
        const uint8_t* wsrc = g_wprep + (size_t)l * W_L_BYTES;
#pragma unroll
        for (int it = 0; it < 16; ++it) {
            uint32_t off = (uint32_t)(it * NTHREADS + tid) * 16u;
            asm volatile("cp.async.cg.shared.global [%0], [%1], 16;"
                         :: "r"(sb + off), "l"(wsrc + off) : "memory");
        }
        asm volatile("cp.async.commit_group;" ::: "memory");
    }

    // Per-thread constants for A conversion
    const int cr = tid >> 5;              // row base 0..3, step 4 per iter
    const int cq = tid & 31;              // float4 column
    const float* aColBase = in + (size_t)m * IN_F + cq * 4;

    // Warp tile: wid&1 -> m block (32 rows), wid>>1 -> n block (64 cols)
    const int m0 = (wid & 1) * 32;
    const int n0 = (wid >> 1) * 64;
    const int row_in = (lane & 7) + ((lane >> 3) & 1) * 8;
    const int kadd   = (lane >> 4) * 8;

    // Bias fragments (m==0 only), nt 0..7
    float2 bv[8];
#pragma unroll
    for (int nt = 0; nt < 8; ++nt) {
        int col = n0 + nt * 8 + (lane & 3) * 2;
        bv[nt].x = (m == 0) ? bias[col]     : 0.0f;
        bv[nt].y = (m == 0) ? bias[col + 1] : 0.0f;
    }

    for (int t = 0; t < NTILE; ++t) {
        const int b0 = (blockIdx.x * NTILE + t) * TILE_B;

        // ---- Convert A tile (64x128 fp32 -> fp16 RN, swizzled); 16 iters ----
#pragma unroll
        for (int it = 0; it < 16; ++it) {
            int r = cr + it * 4;
            uint32_t soff = (uint32_t)(cq >> 4) * A_CH_STRIDE +
                            SWZ((uint32_t)(r * 128 + (cq & 15) * 8));
            float4 v = __ldcs(reinterpret_cast<const float4*>(
                aColBase + (size_t)(b0 + r) * (NUM_M * IN_F)));
            *reinterpret_cast<uint2*>(smem + A_OFF + soff) =
                make_uint2(pack_h2(v.x, v.y), pack_h2(v.z, v.w));
        }
        if (t == 0) asm volatile("cp.async.wait_group 0;" ::: "memory");
        __syncthreads();

        // ---- MMA: 8 k-steps, 16 MMA per warp per step ----
        float acc[2][8][4];
#pragma unroll
        for (int a = 0; a < 2; ++a)
#pragma unroll
            for (int b = 0; b < 8; ++b)
#pragma unroll
                for (int c = 0; c < 4; ++c) acc[a][b][c] = 0.0f;

#pragma unroll
        for (int ks = 0; ks < 8; ++ks) {
            const int kc    = ks * 16 + kadd;
            const int chunk = kc >> 6;
            const int kwi   = (kc & 63) * 2;

            uint32_t ah[2][4], wh[4][4];
#pragma unroll
            for (int mt = 0; mt < 2; ++mt) {
                uint32_t addr = sb + A_OFF + (uint32_t)chunk * A_CH_STRIDE +
                                SWZ((uint32_t)((m0 + mt * 16 + row_in) * 128 + kwi));
                LDSM4(ah[mt], addr);
            }
#pragma unroll
            for (int g = 0; g < 4; ++g) {
                uint32_t addr = sb + (uint32_t)chunk * W_CH_STRIDE +
                                SWZ((uint32_t)((n0 + g * 16 + row_in) * 128 + kwi));
                LDSM4(wh[g], addr);
            }
#pragma unroll
            for (int mt = 0; mt < 2; ++mt) {
#pragma unroll
                for (int nt = 0; nt < 8; ++nt) {
                    const int g = nt >> 1, o = nt & 1;
                    MMA_F16(acc[mt][nt], ah[mt], wh[g][o], wh[g][2 + o]);
                }
            }
        }
        __syncthreads();   // A smem reused by next tile's convert

        // ---- Epilogue: direct STG.64 streaming stores ----
#pragma unroll
        for (int mt = 0; mt < 2; ++mt) {
#pragma unroll
            for (int nt = 0; nt < 8; ++nt) {
#pragma unroll
                for (int h = 0; h < 2; ++h) {
                    int row = b0 + m0 + mt * 16 + (lane >> 2) + h * 8;
                    int col = n0 + nt * 8 + (lane & 3) * 2;
                    float2 v;
                    v.x = acc[mt][nt][2 * h]     + bv[nt].x;
                    v.y = acc[mt][nt][2 * h + 1] + bv[nt].y;
                    __stcs(reinterpret_cast<float2*>(
                               out + ((size_t)row * NUM_M + m) * OUT_F + col), v);
                }
            }
        }
    }
}

extern "C" void kernel_launch(void* const* d_in, const int* in_sizes, int n_in,
                              void* d_out, int out_size) {
    const float* in   = (const float*)d_in[0];  // [16384, 25, 128]
    const float* w    = (const float*)d_in[1];  // [5, 128, 128]
    const float* bias = (const float*)d_in[2];  // [128]
    float* out        = (float*)d_out;          // [16384, 25, 128]

    so3_prep_w<<<5, 256>>>(w);

    cudaFuncSetAttribute(so3linear_hmma_kernel,
                         cudaFuncAttributeMaxDynamicSharedMemorySize, SMEM_BYTES);

    dim3 grid(BATCH / (TILE_B * NTILE), NUM_M);  // (64, 25) = 1600 CTAs
    so3linear_hmma_kernel<<<grid, NTHREADS, SMEM_BYTES>>>(in, bias, out);
}

// round 12
// speedup vs baseline: 1.0144x; 1.0144x over previous
#include <cuda_runtime.h>
#include <cuda_fp16.h>
#include <cstdint>

// SO3Linear via mma.sync fp16 (HMMA), single-MMA scheme (calibrated rel_err ~3e-4).
// R10 = R6 (the 32-warp/SM corner: 48KB smem, 64 regs, 4x256thr/SM) plus
// zero-cost scheduling fixes:
//   - epilogue moved BEFORE the tile-end barrier (register-only; overlaps
//     other warps' MMA tails instead of convoying)
//   - prefetch.global.L2 of next tile's A right after MMA (LDG 600 -> ~250cy)
//   - __ldcs on A (read-once), __stcs on out (write-once): protect L2
//     residency of the prepped W images.

#define BATCH    16384
#define NUM_M    25
#define IN_F     128
#define OUT_F    128
#define TILE_B   64
#define NTILE    4
#define NTHREADS 256

// W image per l: 32KB = 2 k-chunks (k 0..63 | 64..127) of 128 rows x 128B.
#define W_L_BYTES   32768
#define W_CH_STRIDE 16384
// smem: W at 0 (32KB), A at 32KB (2 chunks x 8KB).
#define A_OFF       32768
#define A_CH_STRIDE 8192
#define SMEM_BYTES  49152

#define SWZ(b) ((b) ^ (((b) >> 3) & 0x70))

__device__ __align__(128) uint8_t g_wprep[5 * W_L_BYTES];

__device__ __forceinline__ uint32_t smem_u32(const void* p) {
    uint32_t a;
    asm("{ .reg .u64 t; cvta.to.shared.u64 t, %1; cvt.u32.u64 %0, t; }" : "=r"(a) : "l"(p));
    return a;
}

#define LDSM4(r, addr) \
    asm volatile("ldmatrix.sync.aligned.m8n8.x4.shared.b16 {%0,%1,%2,%3}, [%4];" \
        : "=r"((r)[0]), "=r"((r)[1]), "=r"((r)[2]), "=r"((r)[3]) : "r"(addr))

#define MMA_F16(c, a, b0_, b1_) \
    asm volatile("mma.sync.aligned.m16n8k16.row.col.f32.f16.f16.f32 " \
        "{%0,%1,%2,%3},{%4,%5,%6,%7},{%8,%9},{%0,%1,%2,%3};" \
        : "+f"((c)[0]), "+f"((c)[1]), "+f"((c)[2]), "+f"((c)[3]) \
        : "r"((a)[0]), "r"((a)[1]), "r"((a)[2]), "r"((a)[3]), "r"(b0_), "r"(b1_))

__device__ __forceinline__ uint32_t pack_h2(float x, float y) {
    __half2 p = __floats2half2_rn(x, y);
    return *reinterpret_cast<uint32_t*>(&p);
}

// ---- Prep: W[l] -> centered fp16, SW128 smem-image layout in global ----
__global__ void so3_prep_w(const float* __restrict__ w) {
    const int l   = blockIdx.x;
    const int tid = threadIdx.x;
    const float bound = 0.088388347648318447f;  // 1/sqrt(128)
    uint8_t* dst = g_wprep + (size_t)l * W_L_BYTES;
    const float* src = w + (size_t)l * OUT_F * IN_F;
#pragma unroll
    for (int it = 0; it < 16; ++it) {
        int li = it * 256 + tid;
        int r  = li >> 5;
        int q  = li & 31;
        uint32_t soff = (uint32_t)(q >> 4) * W_CH_STRIDE +
                        SWZ((uint32_t)(r * 128 + (q & 15) * 8));
        float4 v = *reinterpret_cast<const float4*>(src + (size_t)r * IN_F + q * 4);
        v.x -= bound; v.y -= bound; v.z -= bound; v.w -= bound;
        *reinterpret_cast<uint2*>(dst + soff) =
            make_uint2(pack_h2(v.x, v.y), pack_h2(v.z, v.w));
    }
}

// ---- Main kernel ----
__global__ __launch_bounds__(NTHREADS, 4)
void so3linear_hmma_kernel(const float* __restrict__ in,
                           const float* __restrict__ bias,
                           float* __restrict__ out) {
    extern __shared__ char smem[];
    const uint32_t sb = smem_u32(smem);

    const int tid  = threadIdx.x;
    const int wid  = tid >> 5;
    const int lane = tid & 31;
    const int m    = blockIdx.y;
    const int l    = (m >= 16) ? 4 : (m >= 9) ? 3 : (m >= 4) ? 2 : (m >= 1) ? 1 : 0;

    // ---- W: flat 32KB cp.async from prepped image ----
    {
        const uint8_t* wsrc = g_wprep + (size_t)l * W_L_BYTES;
#pragma unroll
        for (int it = 0; it < 8; ++it) {
            uint32_t off = (uint32_t)(it * NTHREADS + tid) * 16u;
            asm volatile("cp.async.cg.shared.global [%0], [%1], 16;"
                         :: "r"(sb + off), "l"(wsrc + off) : "memory");
        }
        asm volatile("cp.async.commit_group;" ::: "memory");
    }

    // Per-thread constants for A conversion
    const int cr = tid >> 5;              // row base 0..7, step 8 per iter
    const int cq = tid & 31;              // float4 column
    const uint32_t a_soff = (uint32_t)(cq >> 4) * A_CH_STRIDE +
                            SWZ((uint32_t)(cr * 128 + (cq & 15) * 8));
    const float* aColBase = in + (size_t)m * IN_F + cq * 4;

    // Warp tile: wid&1 -> m block (32 rows), wid>>1 -> n block (32 cols)
    const int m0 = (wid & 1) * 32;
    const int n0 = (wid >> 1) * 32;
    const int row_in = (lane & 7) + ((lane >> 3) & 1) * 8;
    const int kadd   = (lane >> 4) * 8;

    // Bias fragment (m==0 only)
    float2 bv[4];
#pragma unroll
    for (int nt = 0; nt < 4; ++nt) {
        int col = n0 + nt * 8 + (lane & 3) * 2;
        bv[nt].x = (m == 0) ? bias[col]     : 0.0f;
        bv[nt].y = (m == 0) ? bias[col + 1] : 0.0f;
    }

    for (int t = 0; t < NTILE; ++t) {
        const int b0 = (blockIdx.x * NTILE + t) * TILE_B;

        // ---- Convert A tile (64x128 fp32 -> fp16 RN, swizzled) ----
#pragma unroll
        for (int it = 0; it < 8; ++it) {
            int r = cr + it * 8;
            uint32_t soff = a_soff + (uint32_t)it * (8 * 128);
            float4 v = __ldcs(reinterpret_cast<const float4*>(
                aColBase + (size_t)(b0 + r) * (NUM_M * IN_F)));
            *reinterpret_cast<uint2*>(smem + A_OFF + soff) =
                make_uint2(pack_h2(v.x, v.y), pack_h2(v.z, v.w));
        }
        if (t == 0) asm volatile("cp.async.wait_group 0;" ::: "memory");
        __syncthreads();

        // ---- MMA: 8 k-steps ----
        float acc[2][4][4];
#pragma unroll
        for (int a = 0; a < 2; ++a)
#pragma unroll
            for (int b = 0; b < 4; ++b)
#pragma unroll
                for (int c = 0; c < 4; ++c) acc[a][b][c] = 0.0f;

#pragma unroll
        for (int ks = 0; ks < 8; ++ks) {
            const int kc    = ks * 16 + kadd;
            const int chunk = kc >> 6;
            const int kwi   = (kc & 63) * 2;

            uint32_t ah[2][4], wh[2][4];
#pragma unroll
            for (int mt = 0; mt < 2; ++mt) {
                uint32_t addr = sb + A_OFF + (uint32_t)chunk * A_CH_STRIDE +
                                SWZ((uint32_t)((m0 + mt * 16 + row_in) * 128 + kwi));
                LDSM4(ah[mt], addr);
            }
#pragma unroll
            for (int g = 0; g < 2; ++g) {
                uint32_t addr = sb + (uint32_t)chunk * W_CH_STRIDE +
                                SWZ((uint32_t)((n0 + g * 16 + row_in) * 128 + kwi));
                LDSM4(wh[g], addr);
            }
#pragma unroll
            for (int mt = 0; mt < 2; ++mt) {
#pragma unroll
                for (int nt = 0; nt < 4; ++nt) {
                    const int g = nt >> 1, o = nt & 1;
                    MMA_F16(acc[mt][nt], ah[mt], wh[g][o], wh[g][2 + o]);
                }
            }
        }

        // ---- L2 prefetch of next tile's A (no destination regs) ----
        if (t + 1 < NTILE) {
            const int b0n = b0 + TILE_B;
#pragma unroll
            for (int it = 0; it < 8; ++it) {
                int r = cr + it * 8;
                asm volatile("prefetch.global.L2 [%0];"
                             :: "l"(aColBase + (size_t)(b0n + r) * (NUM_M * IN_F)));
            }
        }

        // ---- Epilogue BEFORE barrier: register-only streaming STG.64 ----
#pragma unroll
        for (int mt = 0; mt < 2; ++mt) {
#pragma unroll
            for (int nt = 0; nt < 4; ++nt) {
#pragma unroll
                for (int h = 0; h < 2; ++h) {
                    int row = b0 + m0 + mt * 16 + (lane >> 2) + h * 8;
                    int col = n0 + nt * 8 + (lane & 3) * 2;
                    float2 v;
                    v.x = acc[mt][nt][2 * h]     + bv[nt].x;
                    v.y = acc[mt][nt][2 * h + 1] + bv[nt].y;
                    __stcs(reinterpret_cast<float2*>(
                               out + ((size_t)row * NUM_M + m) * OUT_F + col), v);
                }
            }
        }

        __syncthreads();   // protect A smem for next tile's convert
    }
}

extern "C" void kernel_launch(void* const* d_in, const int* in_sizes, int n_in,
                              void* d_out, int out_size) {
    const float* in   = (const float*)d_in[0];  // [16384, 25, 128]
    const float* w    = (const float*)d_in[1];  // [5, 128, 128]
    const float* bias = (const float*)d_in[2];  // [128]
    float* out        = (float*)d_out;          // [16384, 25, 128]

    so3_prep_w<<<5, 256>>>(w);

    cudaFuncSetAttribute(so3linear_hmma_kernel,
                         cudaFuncAttributeMaxDynamicSharedMemorySize, SMEM_BYTES);

    dim3 grid(BATCH / (TILE_B * NTILE), NUM_M);  // (64, 25) = 1600 CTAs
    so3linear_hmma_kernel<<<grid, NTHREADS, SMEM_BYTES>>>(in, bias, out);
}

// round 13
// speedup vs baseline: 1.1138x; 1.0980x over previous
#include <cuda_runtime.h>
#include <cuda_fp16.h>
#include <cstdint>

// SO3Linear via mma.sync fp16 (HMMA), single-MMA scheme (calibrated rel_err ~3e-4).
// R11 = R6 exactly (32-warp/SM corner: 48KB smem, 64 regs, 2 barriers/tile,
// plain LDG/STG) + output-column permutation folded into the W-prep kernel:
//   fragment phys col P=(nt<<3)|(q<<1)|j  -> logical col L=(q<<3)|(nt<<1)|j
// so each lane's 8 accum values are CONTIGUOUS output features -> epilogue is
// 8 STG.128 per warp instead of 16 STG.64 (epilogue L1 wavefronts halved).

#define BATCH    16384
#define NUM_M    25
#define IN_F     128
#define OUT_F    128
#define TILE_B   64
#define NTILE    4
#define NTHREADS 256

// W image per l: 32KB = 2 k-chunks (k 0..63 | 64..127) of 128 rows x 128B.
#define W_L_BYTES   32768
#define W_CH_STRIDE 16384
// smem: W at 0 (32KB), A at 32KB (2 chunks x 8KB).
#define A_OFF       32768
#define A_CH_STRIDE 8192
#define SMEM_BYTES  49152

#define SWZ(b) ((b) ^ (((b) >> 3) & 0x70))

__device__ __align__(128) uint8_t g_wprep[5 * W_L_BYTES];

__device__ __forceinline__ uint32_t smem_u32(const void* p) {
    uint32_t a;
    asm("{ .reg .u64 t; cvta.to.shared.u64 t, %1; cvt.u32.u64 %0, t; }" : "=r"(a) : "l"(p));
    return a;
}

#define LDSM4(r, addr) \
    asm volatile("ldmatrix.sync.aligned.m8n8.x4.shared.b16 {%0,%1,%2,%3}, [%4];" \
        : "=r"((r)[0]), "=r"((r)[1]), "=r"((r)[2]), "=r"((r)[3]) : "r"(addr))

#define MMA_F16(c, a, b0_, b1_) \
    asm volatile("mma.sync.aligned.m16n8k16.row.col.f32.f16.f16.f32 " \
        "{%0,%1,%2,%3},{%4,%5,%6,%7},{%8,%9},{%0,%1,%2,%3};" \
        : "+f"((c)[0]), "+f"((c)[1]), "+f"((c)[2]), "+f"((c)[3]) \
        : "r"((a)[0]), "r"((a)[1]), "r"((a)[2]), "r"((a)[3]), "r"(b0_), "r"(b1_))

__device__ __forceinline__ uint32_t pack_h2(float x, float y) {
    __half2 p = __floats2half2_rn(x, y);
    return *reinterpret_cast<uint32_t*>(&p);
}

// Within each 32-row block of the W image, phys row P sources logical feature:
//   L = ((P>>1)&3)<<3 | ((P>>3)&3)<<1 | (P&1)
__device__ __forceinline__ int perm32(int p) {
    return (((p >> 1) & 3) << 3) | (((p >> 3) & 3) << 1) | (p & 1);
}

// ---- Prep: W[l] -> centered fp16, SW128 smem-image layout, rows permuted ----
__global__ void so3_prep_w(const float* __restrict__ w) {
    const int l   = blockIdx.x;
    const int tid = threadIdx.x;
    const float bound = 0.088388347648318447f;  // 1/sqrt(128)
    uint8_t* dst = g_wprep + (size_t)l * W_L_BYTES;
    const float* src = w + (size_t)l * OUT_F * IN_F;
#pragma unroll
    for (int it = 0; it < 16; ++it) {
        int li = it * 256 + tid;
        int r  = li >> 5;                 // dst image row 0..127 (phys)
        int q  = li & 31;                 // float4 col, k0 = 4q
        int rs = (r & ~31) | perm32(r & 31);   // src weight row (logical feature)
        uint32_t soff = (uint32_t)(q >> 4) * W_CH_STRIDE +
                        SWZ((uint32_t)(r * 128 + (q & 15) * 8));
        float4 v = *reinterpret_cast<const float4*>(src + (size_t)rs * IN_F + q * 4);
        v.x -= bound; v.y -= bound; v.z -= bound; v.w -= bound;
        *reinterpret_cast<uint2*>(dst + soff) =
            make_uint2(pack_h2(v.x, v.y), pack_h2(v.z, v.w));
    }
}

// ---- Main kernel ----
__global__ __launch_bounds__(NTHREADS, 4)
void so3linear_hmma_kernel(const float* __restrict__ in,
                           const float* __restrict__ bias,
                           float* __restrict__ out) {
    extern __shared__ char smem[];
    const uint32_t sb = smem_u32(smem);

    const int tid  = threadIdx.x;
    const int wid  = tid >> 5;
    const int lane = tid & 31;
    const int m    = blockIdx.y;
    const int l    = (m >= 16) ? 4 : (m >= 9) ? 3 : (m >= 4) ? 2 : (m >= 1) ? 1 : 0;

    // ---- W: flat 32KB cp.async from prepped image ----
    {
        const uint8_t* wsrc = g_wprep + (size_t)l * W_L_BYTES;
#pragma unroll
        for (int it = 0; it < 8; ++it) {
            uint32_t off = (uint32_t)(it * NTHREADS + tid) * 16u;
            asm volatile("cp.async.cg.shared.global [%0], [%1], 16;"
                         :: "r"(sb + off), "l"(wsrc + off) : "memory");
        }
        asm volatile("cp.async.commit_group;" ::: "memory");
    }

    // Per-thread constants for A conversion
    const int cr = tid >> 5;              // row base 0..7, step 8 per iter
    const int cq = tid & 31;              // float4 column
    const uint32_t a_soff = (uint32_t)(cq >> 4) * A_CH_STRIDE +
                            SWZ((uint32_t)(cr * 128 + (cq & 15) * 8));
    const float* aColBase = in + (size_t)m * IN_F + cq * 4;

    // Warp tile: wid&1 -> m block (32 rows), wid>>1 -> n block (32 cols)
    const int m0 = (wid & 1) * 32;
    const int n0 = (wid >> 1) * 32;
    const int row_in = (lane & 7) + ((lane >> 3) & 1) * 8;
    const int kadd   = (lane >> 4) * 8;

    // This lane owns contiguous output cols n0 + 8*(lane&3) .. +7
    const int colbase = n0 + (lane & 3) * 8;
    float4 bva = make_float4(0.f, 0.f, 0.f, 0.f);
    float4 bvb = make_float4(0.f, 0.f, 0.f, 0.f);
    if (m == 0) {
        bva = *reinterpret_cast<const float4*>(bias + colbase);
        bvb = *reinterpret_cast<const float4*>(bias + colbase + 4);
    }

    for (int t = 0; t < NTILE; ++t) {
        const int b0 = (blockIdx.x * NTILE + t) * TILE_B;

        // ---- Convert A tile (64x128 fp32 -> fp16 RN, swizzled) ----
#pragma unroll
        for (int it = 0; it < 8; ++it) {
            int r = cr + it * 8;
            uint32_t soff = a_soff + (uint32_t)it * (8 * 128);
            float4 v = *reinterpret_cast<const float4*>(
                aColBase + (size_t)(b0 + r) * (NUM_M * IN_F));
            *reinterpret_cast<uint2*>(smem + A_OFF + soff) =
                make_uint2(pack_h2(v.x, v.y), pack_h2(v.z, v.w));
        }
        if (t == 0) asm volatile("cp.async.wait_group 0;" ::: "memory");
        __syncthreads();

        // ---- MMA: 8 k-steps ----
        float acc[2][4][4];
#pragma unroll
        for (int a = 0; a < 2; ++a)
#pragma unroll
            for (int b = 0; b < 4; ++b)
#pragma unroll
                for (int c = 0; c < 4; ++c) acc[a][b][c] = 0.0f;

#pragma unroll
        for (int ks = 0; ks < 8; ++ks) {
            const int kc    = ks * 16 + kadd;
            const int chunk = kc >> 6;
            const int kwi   = (kc & 63) * 2;

            uint32_t ah[2][4], wh[2][4];
#pragma unroll
            for (int mt = 0; mt < 2; ++mt) {
                uint32_t addr = sb + A_OFF + (uint32_t)chunk * A_CH_STRIDE +
                                SWZ((uint32_t)((m0 + mt * 16 + row_in) * 128 + kwi));
                LDSM4(ah[mt], addr);
            }
#pragma unroll
            for (int g = 0; g < 2; ++g) {
                uint32_t addr = sb + (uint32_t)chunk * W_CH_STRIDE +
                                SWZ((uint32_t)((n0 + g * 16 + row_in) * 128 + kwi));
                LDSM4(wh[g], addr);
            }
#pragma unroll
            for (int mt = 0; mt < 2; ++mt) {
#pragma unroll
                for (int nt = 0; nt < 4; ++nt) {
                    const int g = nt >> 1, o = nt & 1;
                    MMA_F16(acc[mt][nt], ah[mt], wh[g][o], wh[g][2 + o]);
                }
            }
        }
        __syncthreads();   // A smem reused by next tile's convert

        // ---- Epilogue: permuted cols -> contiguous; 8x STG.128 per warp ----
        // acc[mt][nt][2h+j] holds output col colbase + 2*nt + j (logical).
#pragma unroll
        for (int mt = 0; mt < 2; ++mt) {
#pragma unroll
            for (int h = 0; h < 2; ++h) {
                int row = b0 + m0 + mt * 16 + (lane >> 2) + h * 8;
                size_t base = ((size_t)row * NUM_M + m) * OUT_F + colbase;
                float4 va, vb;
                va.x = acc[mt][0][2 * h]     + bva.x;
                va.y = acc[mt][0][2 * h + 1] + bva.y;
                va.z = acc[mt][1][2 * h]     + bva.z;
                va.w = acc[mt][1][2 * h + 1] + bva.w;
                vb.x = acc[mt][2][2 * h]     + bvb.x;
                vb.y = acc[mt][2][2 * h + 1] + bvb.y;
                vb.z = acc[mt][3][2 * h]     + bvb.z;
                vb.w = acc[mt][3][2 * h + 1] + bvb.w;
                *reinterpret_cast<float4*>(out + base)     = va;
                *reinterpret_cast<float4*>(out + base + 4) = vb;
            }
        }
    }
}

extern "C" void kernel_launch(void* const* d_in, const int* in_sizes, int n_in,
                              void* d_out, int out_size) {
    const float* in   = (const float*)d_in[0];  // [16384, 25, 128]
    const float* w    = (const float*)d_in[1];  // [5, 128, 128]
    const float* bias = (const float*)d_in[2];  // [128]
    float* out        = (float*)d_out;          // [16384, 25, 128]

    so3_prep_w<<<5, 256>>>(w);

    cudaFuncSetAttribute(so3linear_hmma_kernel,
                         cudaFuncAttributeMaxDynamicSharedMemorySize, SMEM_BYTES);

    dim3 grid(BATCH / (TILE_B * NTILE), NUM_M);  // (64, 25) = 1600 CTAs
    so3linear_hmma_kernel<<<grid, NTHREADS, SMEM_BYTES>>>(in, bias, out);
}

// round 16
// speedup vs baseline: 1.1281x; 1.0128x over previous
#include <cuda_runtime.h>
#include <cuda_fp16.h>
#include <cstdint>

// SO3Linear via mma.sync fp16 (HMMA), single-MMA scheme (calibrated rel_err ~3e-4).
// R12 = R11 (R6 corner + permuted-output STG.128 epilogue) + first-wave CTA
// phase staggering: co-resident CTA quartets on an SM are bids {s,s+148,s+296,
// s+444} (classic LUT placement), all launched in lockstep with identical
// phase structure -> convert/MMA/epilogue phases convoy and resources burst
// alternately. Spin-delaying wave w (=bid/148, w<4) by w*3000 cycles
// interleaves the phases across siblings. Zero regs/smem/barrier cost.

#define BATCH    16384
#define NUM_M    25
#define IN_F     128
#define OUT_F    128
#define TILE_B   64
#define NTILE    4
#define NTHREADS 256

#define W_L_BYTES   32768
#define W_CH_STRIDE 16384
#define A_OFF       32768
#define A_CH_STRIDE 8192
#define SMEM_BYTES  49152

#define SWZ(b) ((b) ^ (((b) >> 3) & 0x70))

__device__ __align__(128) uint8_t g_wprep[5 * W_L_BYTES];

__device__ __forceinline__ uint32_t smem_u32(const void* p) {
    uint32_t a;
    asm("{ .reg .u64 t; cvta.to.shared.u64 t, %1; cvt.u32.u64 %0, t; }" : "=r"(a) : "l"(p));
    return a;
}

#define LDSM4(r, addr) \
    asm volatile("ldmatrix.sync.aligned.m8n8.x4.shared.b16 {%0,%1,%2,%3}, [%4];" \
        : "=r"((r)[0]), "=r"((r)[1]), "=r"((r)[2]), "=r"((r)[3]) : "r"(addr))

#define MMA_F16(c, a, b0_, b1_) \
    asm volatile("mma.sync.aligned.m16n8k16.row.col.f32.f16.f16.f32 " \
        "{%0,%1,%2,%3},{%4,%5,%6,%7},{%8,%9},{%0,%1,%2,%3};" \
        : "+f"((c)[0]), "+f"((c)[1]), "+f"((c)[2]), "+f"((c)[3]) \
        : "r"((a)[0]), "r"((a)[1]), "r"((a)[2]), "r"((a)[3]), "r"(b0_), "r"(b1_))

__device__ __forceinline__ uint32_t pack_h2(float x, float y) {
    __half2 p = __floats2half2_rn(x, y);
    return *reinterpret_cast<uint32_t*>(&p);
}

// Within each 32-row block of the W image, phys row P sources logical feature:
//   L = ((P>>1)&3)<<3 | ((P>>3)&3)<<1 | (P&1)
__device__ __forceinline__ int perm32(int p) {
    return (((p >> 1) & 3) << 3) | (((p >> 3) & 3) << 1) | (p & 1);
}

// ---- Prep: W[l] -> centered fp16, SW128 smem-image layout, rows permuted ----
__global__ void so3_prep_w(const float* __restrict__ w) {
    const int l   = blockIdx.x;
    const int tid = threadIdx.x;
    const float bound = 0.088388347648318447f;  // 1/sqrt(128)
    uint8_t* dst = g_wprep + (size_t)l * W_L_BYTES;
    const float* src = w + (size_t)l * OUT_F * IN_F;
#pragma unroll
    for (int it = 0; it < 16; ++it) {
        int li = it * 256 + tid;
        int r  = li >> 5;
        int q  = li & 31;
        int rs = (r & ~31) | perm32(r & 31);
        uint32_t soff = (uint32_t)(q >> 4) * W_CH_STRIDE +
                        SWZ((uint32_t)(r * 128 + (q & 15) * 8));
        float4 v = *reinterpret_cast<const float4*>(src + (size_t)rs * IN_F + q * 4);
        v.x -= bound; v.y -= bound; v.z -= bound; v.w -= bound;
        *reinterpret_cast<uint2*>(dst + soff) =
            make_uint2(pack_h2(v.x, v.y), pack_h2(v.z, v.w));
    }
}

// ---- Main kernel ----
__global__ __launch_bounds__(NTHREADS, 4)
void so3linear_hmma_kernel(const float* __restrict__ in,
                           const float* __restrict__ bias,
                           float* __restrict__ out) {
    extern __shared__ char smem[];
    const uint32_t sb = smem_u32(smem);

    const int tid  = threadIdx.x;
    const int wid  = tid >> 5;
    const int lane = tid & 31;
    const int m    = blockIdx.y;
    const int l    = (m >= 16) ? 4 : (m >= 9) ? 3 : (m >= 4) ? 2 : (m >= 1) ? 1 : 0;

    // ---- W: flat 32KB cp.async from prepped image (issue before stagger) ----
    {
        const uint8_t* wsrc = g_wprep + (size_t)l * W_L_BYTES;
#pragma unroll
        for (int it = 0; it < 8; ++it) {
            uint32_t off = (uint32_t)(it * NTHREADS + tid) * 16u;
            asm volatile("cp.async.cg.shared.global [%0], [%1], 16;"
                         :: "r"(sb + off), "l"(wsrc + off) : "memory");
        }
        asm volatile("cp.async.commit_group;" ::: "memory");
    }

    // ---- Phase stagger: desync co-resident CTA quartets (bids s+148k) ----
    {
        int bid  = blockIdx.y * gridDim.x + blockIdx.x;
        int wave = bid / 148;
        if (wave >= 1 && wave < 4) {
            long long dl = (long long)wave * 3000;
            long long t0 = clock64();
            while (clock64() - t0 < dl) { }
        }
    }

    // Per-thread constants for A conversion
    const int cr = tid >> 5;
    const int cq = tid & 31;
    const uint32_t a_soff = (uint32_t)(cq >> 4) * A_CH_STRIDE +
                            SWZ((uint32_t)(cr * 128 + (cq & 15) * 8));
    const float* aColBase = in + (size_t)m * IN_F + cq * 4;

    // Warp tile: wid&1 -> m block (32 rows), wid>>1 -> n block (32 cols)
    const int m0 = (wid & 1) * 32;
    const int n0 = (wid >> 1) * 32;
    const int row_in = (lane & 7) + ((lane >> 3) & 1) * 8;
    const int kadd   = (lane >> 4) * 8;

    // This lane owns contiguous output cols n0 + 8*(lane&3) .. +7
    const int colbase = n0 + (lane & 3) * 8;
    float4 bva = make_float4(0.f, 0.f, 0.f, 0.f);
    float4 bvb = make_float4(0.f, 0.f, 0.f, 0.f);
    if (m == 0) {
        bva = *reinterpret_cast<const float4*>(bias + colbase);
        bvb = *reinterpret_cast<const float4*>(bias + colbase + 4);
    }

    for (int t = 0; t < NTILE; ++t) {
        const int b0 = (blockIdx.x * NTILE + t) * TILE_B;

        // ---- Convert A tile (64x128 fp32 -> fp16 RN, swizzled) ----
#pragma unroll
        for (int it = 0; it < 8; ++it) {
            int r = cr + it * 8;
            uint32_t soff = a_soff + (uint32_t)it * (8 * 128);
            float4 v = *reinterpret_cast<const float4*>(
                aColBase + (size_t)(b0 + r) * (NUM_M * IN_F));
            *reinterpret_cast<uint2*>(smem + A_OFF + soff) =
                make_uint2(pack_h2(v.x, v.y), pack_h2(v.z, v.w));
        }
        if (t == 0) asm volatile("cp.async.wait_group 0;" ::: "memory");
        __syncthreads();

        // ---- MMA: 8 k-steps ----
        float acc[2][4][4];
#pragma unroll
        for (int a = 0; a < 2; ++a)
#pragma unroll
            for (int b = 0; b < 4; ++b)
#pragma unroll
                for (int c = 0; c < 4; ++c) acc[a][b][c] = 0.0f;

#pragma unroll
        for (int ks = 0; ks < 8; ++ks) {
            const int kc    = ks * 16 + kadd;
            const int chunk = kc >> 6;
            const int kwi   = (kc & 63) * 2;

            uint32_t ah[2][4], wh[2][4];
#pragma unroll
            for (int mt = 0; mt < 2; ++mt) {
                uint32_t addr = sb + A_OFF + (uint32_t)chunk * A_CH_STRIDE +
                                SWZ((uint32_t)((m0 + mt * 16 + row_in) * 128 + kwi));
                LDSM4(ah[mt], addr);
            }
#pragma unroll
            for (int g = 0; g < 2; ++g) {
                uint32_t addr = sb + (uint32_t)chunk * W_CH_STRIDE +
                                SWZ((uint32_t)((n0 + g * 16 + row_in) * 128 + kwi));
                LDSM4(wh[g], addr);
            }
#pragma unroll
            for (int mt = 0; mt < 2; ++mt) {
#pragma unroll
                for (int nt = 0; nt < 4; ++nt) {
                    const int g = nt >> 1, o = nt & 1;
                    MMA_F16(acc[mt][nt], ah[mt], wh[g][o], wh[g][2 + o]);
                }
            }
        }
        __syncthreads();   // A smem reused by next tile's convert

        // ---- Epilogue: permuted cols -> contiguous; 8x STG.128 per warp ----
#pragma unroll
        for (int mt = 0; mt < 2; ++mt) {
#pragma unroll
            for (int h = 0; h < 2; ++h) {
                int row = b0 + m0 + mt * 16 + (lane >> 2) + h * 8;
                size_t base = ((size_t)row * NUM_M + m) * OUT_F + colbase;
                float4 va, vb;
                va.x = acc[mt][0][2 * h]     + bva.x;
                va.y = acc[mt][0][2 * h + 1] + bva.y;
                va.z = acc[mt][1][2 * h]     + bva.z;
                va.w = acc[mt][1][2 * h + 1] + bva.w;
                vb.x = acc[mt][2][2 * h]     + bvb.x;
                vb.y = acc[mt][2][2 * h + 1] + bvb.y;
                vb.z = acc[mt][3][2 * h]     + bvb.z;
                vb.w = acc[mt][3][2 * h + 1] + bvb.w;
                *reinterpret_cast<float4*>(out + base)     = va;
                *reinterpret_cast<float4*>(out + base + 4) = vb;
            }
        }
    }
}

extern "C" void kernel_launch(void* const* d_in, const int* in_sizes, int n_in,
                              void* d_out, int out_size) {
    const float* in   = (const float*)d_in[0];  // [16384, 25, 128]
    const float* w    = (const float*)d_in[1];  // [5, 128, 128]
    const float* bias = (const float*)d_in[2];  // [128]
    float* out        = (float*)d_out;          // [16384, 25, 128]

    so3_prep_w<<<5, 256>>>(w);

    cudaFuncSetAttribute(so3linear_hmma_kernel,
                         cudaFuncAttributeMaxDynamicSharedMemorySize, SMEM_BYTES);

    dim3 grid(BATCH / (TILE_B * NTILE), NUM_M);  // (64, 25) = 1600 CTAs
    so3linear_hmma_kernel<<<grid, NTHREADS, SMEM_BYTES>>>(in, bias, out);
}

// round 17
// speedup vs baseline: 1.3962x; 1.2376x over previous
#include <cuda_runtime.h>
#include <cuda_fp16.h>
#include <cstdint>

// SO3Linear via mma.sync fp16 (HMMA), single-MMA scheme (calibrated rel_err ~3e-4).
// R13: NTILE=1 — the tile loop WAS the phase-locking device (4 co-resident
// CTAs iterating identical 4-phase loops in lockstep for their whole life;
// barriers re-lock any offset). One tile per CTA means retire->relaunch gives
// continuous, completion-driven stagger: a fresh CTA's load phase overlaps
// siblings' MMA/epilogue. 6400 CTAs, ~10.8 waves, ONE barrier per CTA.
// W refill per CTA is L2-hit cp.async (images 160KB hot); DRAM unchanged.
// Keeps R11's permuted-output STG.128 epilogue and the 48KB/64-reg corner.

#define BATCH    16384
#define NUM_M    25
#define IN_F     128
#define OUT_F    128
#define TILE_B   64
#define NTHREADS 256

#define W_L_BYTES   32768
#define W_CH_STRIDE 16384
#define A_OFF       32768
#define A_CH_STRIDE 8192
#define SMEM_BYTES  49152

#define SWZ(b) ((b) ^ (((b) >> 3) & 0x70))

__device__ __align__(128) uint8_t g_wprep[5 * W_L_BYTES];

__device__ __forceinline__ uint32_t smem_u32(const void* p) {
    uint32_t a;
    asm("{ .reg .u64 t; cvta.to.shared.u64 t, %1; cvt.u32.u64 %0, t; }" : "=r"(a) : "l"(p));
    return a;
}

#define LDSM4(r, addr) \
    asm volatile("ldmatrix.sync.aligned.m8n8.x4.shared.b16 {%0,%1,%2,%3}, [%4];" \
        : "=r"((r)[0]), "=r"((r)[1]), "=r"((r)[2]), "=r"((r)[3]) : "r"(addr))

#define MMA_F16(c, a, b0_, b1_) \
    asm volatile("mma.sync.aligned.m16n8k16.row.col.f32.f16.f16.f32 " \
        "{%0,%1,%2,%3},{%4,%5,%6,%7},{%8,%9},{%0,%1,%2,%3};" \
        : "+f"((c)[0]), "+f"((c)[1]), "+f"((c)[2]), "+f"((c)[3]) \
        : "r"((a)[0]), "r"((a)[1]), "r"((a)[2]), "r"((a)[3]), "r"(b0_), "r"(b1_))

__device__ __forceinline__ uint32_t pack_h2(float x, float y) {
    __half2 p = __floats2half2_rn(x, y);
    return *reinterpret_cast<uint32_t*>(&p);
}

// Within each 32-row block of the W image, phys row P sources logical feature:
//   L = ((P>>1)&3)<<3 | ((P>>3)&3)<<1 | (P&1)
__device__ __forceinline__ int perm32(int p) {
    return (((p >> 1) & 3) << 3) | (((p >> 3) & 3) << 1) | (p & 1);
}

// ---- Prep: W[l] -> centered fp16, SW128 smem-image layout, rows permuted ----
__global__ void so3_prep_w(const float* __restrict__ w) {
    const int l   = blockIdx.x;
    const int tid = threadIdx.x;
    const float bound = 0.088388347648318447f;  // 1/sqrt(128)
    uint8_t* dst = g_wprep + (size_t)l * W_L_BYTES;
    const float* src = w + (size_t)l * OUT_F * IN_F;
#pragma unroll
    for (int it = 0; it < 16; ++it) {
        int li = it * 256 + tid;
        int r  = li >> 5;
        int q  = li & 31;
        int rs = (r & ~31) | perm32(r & 31);
        uint32_t soff = (uint32_t)(q >> 4) * W_CH_STRIDE +
                        SWZ((uint32_t)(r * 128 + (q & 15) * 8));
        float4 v = *reinterpret_cast<const float4*>(src + (size_t)rs * IN_F + q * 4);
        v.x -= bound; v.y -= bound; v.z -= bound; v.w -= bound;
        *reinterpret_cast<uint2*>(dst + soff) =
            make_uint2(pack_h2(v.x, v.y), pack_h2(v.z, v.w));
    }
}

// ---- Main kernel: one 64-row tile per CTA ----
__global__ __launch_bounds__(NTHREADS, 4)
void so3linear_hmma_kernel(const float* __restrict__ in,
                           const float* __restrict__ bias,
                           float* __restrict__ out) {
    extern __shared__ char smem[];
    const uint32_t sb = smem_u32(smem);

    const int tid  = threadIdx.x;
    const int wid  = tid >> 5;
    const int lane = tid & 31;
    const int m    = blockIdx.y;
    const int l    = (m >= 16) ? 4 : (m >= 9) ? 3 : (m >= 4) ? 2 : (m >= 1) ? 1 : 0;
    const int b0   = blockIdx.x * TILE_B;

    // ---- W: flat 32KB cp.async (L2-hit; overlaps A LDG+convert below) ----
    {
        const uint8_t* wsrc = g_wprep + (size_t)l * W_L_BYTES;
#pragma unroll
        for (int it = 0; it < 8; ++it) {
            uint32_t off = (uint32_t)(it * NTHREADS + tid) * 16u;
            asm volatile("cp.async.cg.shared.global [%0], [%1], 16;"
                         :: "r"(sb + off), "l"(wsrc + off) : "memory");
        }
        asm volatile("cp.async.commit_group;" ::: "memory");
    }

    // ---- Convert A tile (64x128 fp32 -> fp16 RN, swizzled) ----
    {
        const int cr = tid >> 5;
        const int cq = tid & 31;
        const uint32_t a_soff = (uint32_t)(cq >> 4) * A_CH_STRIDE +
                                SWZ((uint32_t)(cr * 128 + (cq & 15) * 8));
        const float* aColBase = in + (size_t)m * IN_F + cq * 4;
#pragma unroll
        for (int it = 0; it < 8; ++it) {
            int r = cr + it * 8;
            uint32_t soff = a_soff + (uint32_t)it * (8 * 128);
            float4 v = *reinterpret_cast<const float4*>(
                aColBase + (size_t)(b0 + r) * (NUM_M * IN_F));
            *reinterpret_cast<uint2*>(smem + A_OFF + soff) =
                make_uint2(pack_h2(v.x, v.y), pack_h2(v.z, v.w));
        }
    }
    asm volatile("cp.async.wait_group 0;" ::: "memory");
    __syncthreads();           // the ONLY barrier in this kernel

    // Warp tile: wid&1 -> m block (32 rows), wid>>1 -> n block (32 cols)
    const int m0 = (wid & 1) * 32;
    const int n0 = (wid >> 1) * 32;
    const int row_in = (lane & 7) + ((lane >> 3) & 1) * 8;
    const int kadd   = (lane >> 4) * 8;

    // ---- MMA: 8 k-steps ----
    float acc[2][4][4];
#pragma unroll
    for (int a = 0; a < 2; ++a)
#pragma unroll
        for (int b = 0; b < 4; ++b)
#pragma unroll
            for (int c = 0; c < 4; ++c) acc[a][b][c] = 0.0f;

#pragma unroll
    for (int ks = 0; ks < 8; ++ks) {
        const int kc    = ks * 16 + kadd;
        const int chunk = kc >> 6;
        const int kwi   = (kc & 63) * 2;

        uint32_t ah[2][4], wh[2][4];
#pragma unroll
        for (int mt = 0; mt < 2; ++mt) {
            uint32_t addr = sb + A_OFF + (uint32_t)chunk * A_CH_STRIDE +
                            SWZ((uint32_t)((m0 + mt * 16 + row_in) * 128 + kwi));
            LDSM4(ah[mt], addr);
        }
#pragma unroll
        for (int g = 0; g < 2; ++g) {
            uint32_t addr = sb + (uint32_t)chunk * W_CH_STRIDE +
                            SWZ((uint32_t)((n0 + g * 16 + row_in) * 128 + kwi));
            LDSM4(wh[g], addr);
        }
#pragma unroll
        for (int mt = 0; mt < 2; ++mt) {
#pragma unroll
            for (int nt = 0; nt < 4; ++nt) {
                const int g = nt >> 1, o = nt & 1;
                MMA_F16(acc[mt][nt], ah[mt], wh[g][o], wh[g][2 + o]);
            }
        }
    }

    // ---- Epilogue: permuted cols -> contiguous; 8x STG.128 per warp ----
    const int colbase = n0 + (lane & 3) * 8;
    float4 bva = make_float4(0.f, 0.f, 0.f, 0.f);
    float4 bvb = make_float4(0.f, 0.f, 0.f, 0.f);
    if (m == 0) {
        bva = *reinterpret_cast<const float4*>(bias + colbase);
        bvb = *reinterpret_cast<const float4*>(bias + colbase + 4);
    }
#pragma unroll
    for (int mt = 0; mt < 2; ++mt) {
#pragma unroll
        for (int h = 0; h < 2; ++h) {
            int row = b0 + m0 + mt * 16 + (lane >> 2) + h * 8;
            size_t base = ((size_t)row * NUM_M + m) * OUT_F + colbase;
            float4 va, vb;
            va.x = acc[mt][0][2 * h]     + bva.x;
            va.y = acc[mt][0][2 * h + 1] + bva.y;
            va.z = acc[mt][1][2 * h]     + bva.z;
            va.w = acc[mt][1][2 * h + 1] + bva.w;
            vb.x = acc[mt][2][2 * h]     + bvb.x;
            vb.y = acc[mt][2][2 * h + 1] + bvb.y;
            vb.z = acc[mt][3][2 * h]     + bvb.z;
            vb.w = acc[mt][3][2 * h + 1] + bvb.w;
            *reinterpret_cast<float4*>(out + base)     = va;
            *reinterpret_cast<float4*>(out + base + 4) = vb;
        }
    }
}

extern "C" void kernel_launch(void* const* d_in, const int* in_sizes, int n_in,
                              void* d_out, int out_size) {
    const float* in   = (const float*)d_in[0];  // [16384, 25, 128]
    const float* w    = (const float*)d_in[1];  // [5, 128, 128]
    const float* bias = (const float*)d_in[2];  // [128]
    float* out        = (float*)d_out;          // [16384, 25, 128]

    so3_prep_w<<<5, 256>>>(w);

    cudaFuncSetAttribute(so3linear_hmma_kernel,
                         cudaFuncAttributeMaxDynamicSharedMemorySize, SMEM_BYTES);

    dim3 grid(BATCH / TILE_B, NUM_M);  // (256, 25) = 6400 CTAs, one tile each
    so3linear_hmma_kernel<<<grid, NTHREADS, SMEM_BYTES>>>(in, bias, out);
}